// round 2
// baseline (speedup 1.0000x reference)
#include <cuda_runtime.h>

#define TT 2048
#define BB 16
#define DD 1024
#define NN 64
#define MT (TT * BB)      // 32768 rows
#define NC 256            // k|v|q|a packed columns

// Scratch for projections: [m][0:64 k | 64:128 v | 128:192 q | 192:256 a]
__device__ float g_proj[(size_t)MT * NC];

// ---------------------------------------------------------------------------
// Phase 1: C[32768, 256] = X[32768,1024] * Wcat^T, fp32 smem-tiled GEMM.
// Each blockIdx.y selects one of the 4 weight matrices (exactly 64 cols each).
// ---------------------------------------------------------------------------
#define BM 128
#define BN 64
#define BK 32

__global__ __launch_bounds__(256) void proj_gemm(
    const float* __restrict__ x,
    const float* __restrict__ Wk, const float* __restrict__ Wv,
    const float* __restrict__ Wq, const float* __restrict__ Wa)
{
    __shared__ float As[BK][BM + 4];   // A transposed: As[k][row]
    __shared__ float Bs[BK][BN + 4];   // Bs[k][col]

    const int cb = blockIdx.y;
    const float* __restrict__ W = (cb == 0) ? Wk : (cb == 1) ? Wv : (cb == 2) ? Wq : Wa;
    const int row0 = blockIdx.x * BM;
    const int tid = threadIdx.x;
    const int tr = tid >> 4;     // 0..15  -> 8 output rows each
    const int tc = tid & 15;     // 0..15  -> 4 output cols each

    float acc[8][4];
#pragma unroll
    for (int ii = 0; ii < 8; ii++)
#pragma unroll
        for (int jj = 0; jj < 4; jj++) acc[ii][jj] = 0.0f;

    for (int k0 = 0; k0 < DD; k0 += BK) {
        // Load A tile: 128x32 floats = 1024 float4, 4 per thread
#pragma unroll
        for (int l = 0; l < 4; l++) {
            int f = tid + 256 * l;
            int r = f >> 3;
            int c4 = (f & 7) << 2;
            float4 v = *(const float4*)(x + (size_t)(row0 + r) * DD + k0 + c4);
            As[c4 + 0][r] = v.x; As[c4 + 1][r] = v.y;
            As[c4 + 2][r] = v.z; As[c4 + 3][r] = v.w;
        }
        // Load B tile: 64x32 floats = 512 float4, 2 per thread
#pragma unroll
        for (int l = 0; l < 2; l++) {
            int f = tid + 256 * l;
            int r = f >> 3;
            int c4 = (f & 7) << 2;
            float4 v = *(const float4*)(W + (size_t)r * DD + k0 + c4);
            Bs[c4 + 0][r] = v.x; Bs[c4 + 1][r] = v.y;
            Bs[c4 + 2][r] = v.z; Bs[c4 + 3][r] = v.w;
        }
        __syncthreads();

#pragma unroll
        for (int k = 0; k < BK; k++) {
            float a[8], bfr[4];
#pragma unroll
            for (int ii = 0; ii < 8; ii++) a[ii] = As[k][tr * 8 + ii];
#pragma unroll
            for (int jj = 0; jj < 4; jj++) bfr[jj] = Bs[k][tc * 4 + jj];
#pragma unroll
            for (int ii = 0; ii < 8; ii++)
#pragma unroll
                for (int jj = 0; jj < 4; jj++)
                    acc[ii][jj] = fmaf(a[ii], bfr[jj], acc[ii][jj]);
        }
        __syncthreads();
    }

#pragma unroll
    for (int ii = 0; ii < 8; ii++)
#pragma unroll
        for (int jj = 0; jj < 4; jj++)
            g_proj[(size_t)(row0 + tr * 8 + ii) * NC + cb * 64 + tc * 4 + jj] = acc[ii][jj];
}

// ---------------------------------------------------------------------------
// Phase 2: sequential scan. One block per batch. Quad (4 threads) per row:
// each thread holds 16 S elements in registers. No __syncthreads needed —
// rows are independent within a step. Cross-quad reduce via SHFL.BFLY.
// Next-step k/q/v/a prefetched one step ahead (covers L2 latency).
// ---------------------------------------------------------------------------
__global__ __launch_bounds__(256) void scan_kernel(
    const float* __restrict__ S_in,
    const float* __restrict__ dA,
    const float* __restrict__ bA,
    float* __restrict__ out)   // [T*B*N] output, then [B*N*N] S_final
{
    const int b = blockIdx.x;
    const int tid = threadIdx.x;
    const int i = tid >> 2;      // row 0..63
    const int c = tid & 3;       // quad lane
    const int j0 = c << 4;       // column chunk start

    float S[16];
    {
        const float* sp = S_in + ((size_t)b * NN + i) * NN + j0;
#pragma unroll
        for (int r = 0; r < 16; r++) S[r] = sp[r];
    }

    const float da = dA[i];
    const float ba = bA[i];

    float kk[16], qq[16], vcur, acur;
    {
        const float* P = g_proj + (size_t)b * NC;   // t = 0
#pragma unroll
        for (int l = 0; l < 4; l++) {
            float4 f = *(const float4*)(P + j0 + 4 * l);
            kk[4 * l + 0] = f.x; kk[4 * l + 1] = f.y; kk[4 * l + 2] = f.z; kk[4 * l + 3] = f.w;
            float4 g = *(const float4*)(P + 128 + j0 + 4 * l);
            qq[4 * l + 0] = g.x; qq[4 * l + 1] = g.y; qq[4 * l + 2] = g.z; qq[4 * l + 3] = g.w;
        }
        vcur = P[64 + i];
        acur = P[192 + i];
    }

    for (int t = 0; t < TT; t++) {
        // --- prefetch t+1 (independent of the S chain) ---
        int tn = (t + 1 < TT) ? t + 1 : t;
        const float* Pn = g_proj + ((size_t)tn * BB + b) * NC;
        float4 nk[4], nq[4];
#pragma unroll
        for (int l = 0; l < 4; l++) {
            nk[l] = *(const float4*)(Pn + j0 + 4 * l);
            nq[l] = *(const float4*)(Pn + 128 + j0 + 4 * l);
        }
        float nv = Pn[64 + i];
        float na = Pn[192 + i];

        // --- retrieved[i] = sum_j S[i][j] * k[j] ---
        float r0 = 0.f, r1 = 0.f, r2 = 0.f, r3 = 0.f;
#pragma unroll
        for (int r = 0; r < 4; r++) {
            r0 = fmaf(S[r],      kk[r],      r0);
            r1 = fmaf(S[4 + r],  kk[4 + r],  r1);
            r2 = fmaf(S[8 + r],  kk[8 + r],  r2);
            r3 = fmaf(S[12 + r], kk[12 + r], r3);
        }
        float rr = (r0 + r1) + (r2 + r3);
        rr += __shfl_xor_sync(0xFFFFFFFFu, rr, 1);
        rr += __shfl_xor_sync(0xFFFFFFFFu, rr, 2);

        // --- gate ---
        float xg = fmaf(da, rr, acur + ba);
        float alpha = __fdividef(1.0f, 1.0f + __expf(-xg));
        float cc = (1.0f - alpha) * vcur;

        // --- fused S update + out = S_new @ q ---
        float o0 = 0.f, o1 = 0.f, o2 = 0.f, o3 = 0.f;
#pragma unroll
        for (int r = 0; r < 4; r++) {
            S[r]      = fmaf(alpha, S[r],      cc * kk[r]);
            S[4 + r]  = fmaf(alpha, S[4 + r],  cc * kk[4 + r]);
            S[8 + r]  = fmaf(alpha, S[8 + r],  cc * kk[8 + r]);
            S[12 + r] = fmaf(alpha, S[12 + r], cc * kk[12 + r]);
            o0 = fmaf(S[r],      qq[r],      o0);
            o1 = fmaf(S[4 + r],  qq[4 + r],  o1);
            o2 = fmaf(S[8 + r],  qq[8 + r],  o2);
            o3 = fmaf(S[12 + r], qq[12 + r], o3);
        }
        float oo = (o0 + o1) + (o2 + o3);
        oo += __shfl_xor_sync(0xFFFFFFFFu, oo, 1);
        oo += __shfl_xor_sync(0xFFFFFFFFu, oo, 2);

        // --- y = o * silu(o) = o^2 * sigmoid(o), off the recurrence chain ---
        if (c == 0) {
            float sg = __fdividef(oo, 1.0f + __expf(-oo));   // silu(oo)
            out[((size_t)t * BB + b) * NN + i] = oo * sg;
        }

        // rotate prefetched operands in
#pragma unroll
        for (int l = 0; l < 4; l++) {
            kk[4 * l + 0] = nk[l].x; kk[4 * l + 1] = nk[l].y;
            kk[4 * l + 2] = nk[l].z; kk[4 * l + 3] = nk[l].w;
            qq[4 * l + 0] = nq[l].x; qq[4 * l + 1] = nq[l].y;
            qq[4 * l + 2] = nq[l].z; qq[4 * l + 3] = nq[l].w;
        }
        vcur = nv; acur = na;
    }

    // S_final after output[T,B,N]
    float* so = out + (size_t)TT * BB * NN + ((size_t)b * NN + i) * NN + j0;
#pragma unroll
    for (int r = 0; r < 16; r++) so[r] = S[r];
}

extern "C" void kernel_launch(void* const* d_in, const int* in_sizes, int n_in,
                              void* d_out, int out_size) {
    const float* x  = (const float*)d_in[0];
    const float* S  = (const float*)d_in[1];
    const float* Wk = (const float*)d_in[2];
    const float* Wv = (const float*)d_in[3];
    const float* Wq = (const float*)d_in[4];
    const float* Wa = (const float*)d_in[5];
    const float* da = (const float*)d_in[6];
    const float* ba = (const float*)d_in[7];
    float* out = (float*)d_out;

    dim3 ggrid(MT / BM, 4);
    proj_gemm<<<ggrid, 256>>>(x, Wk, Wv, Wq, Wa);
    scan_kernel<<<BB, 256>>>(S, da, ba, out);
}

// round 3
// speedup vs baseline: 1.5672x; 1.5672x over previous
#include <cuda_runtime.h>
#include <cuda_bf16.h>
#include <cstdint>

#define TT 2048
#define BB 16
#define DD 1024
#define NN 64
#define MT (TT * BB)      // 32768 rows
#define NC 256            // k|v|q|a packed columns

// ------------------------- device scratch (no allocs allowed) ---------------
__device__ float g_proj[(size_t)MT * NC];                 // 32 MB
__device__ __nv_bfloat16 g_xhi[(size_t)MT * DD];          // 64 MB
__device__ __nv_bfloat16 g_xlo[(size_t)MT * DD];          // 64 MB
__device__ __nv_bfloat16 g_whi[(size_t)NC * DD];          // 512 KB
__device__ __nv_bfloat16 g_wlo[(size_t)NC * DD];          // 512 KB

// ---------------------------------------------------------------------------
// Convert X -> bf16 hi/lo split.  x = hi + lo + O(2^-18 * |x|)
// ---------------------------------------------------------------------------
__global__ __launch_bounds__(256) void convert_x(const float* __restrict__ x) {
    size_t t = (size_t)blockIdx.x * blockDim.x + threadIdx.x;   // one per 16 elems
    size_t base = t * 16;
#pragma unroll
    for (int l = 0; l < 4; l++) {
        float4 v = *(const float4*)(x + base + l * 4);
        __nv_bfloat16 h0 = __float2bfloat16(v.x);
        __nv_bfloat16 h1 = __float2bfloat16(v.y);
        __nv_bfloat16 h2 = __float2bfloat16(v.z);
        __nv_bfloat16 h3 = __float2bfloat16(v.w);
        __nv_bfloat16 l0 = __float2bfloat16(v.x - __bfloat162float(h0));
        __nv_bfloat16 l1 = __float2bfloat16(v.y - __bfloat162float(h1));
        __nv_bfloat16 l2 = __float2bfloat16(v.z - __bfloat162float(h2));
        __nv_bfloat16 l3 = __float2bfloat16(v.w - __bfloat162float(h3));
        __nv_bfloat162 hp0 = __halves2bfloat162(h0, h1);
        __nv_bfloat162 hp1 = __halves2bfloat162(h2, h3);
        __nv_bfloat162 lp0 = __halves2bfloat162(l0, l1);
        __nv_bfloat162 lp1 = __halves2bfloat162(l2, l3);
        *(uint2*)&g_xhi[base + l * 4] = make_uint2(*(uint32_t*)&hp0, *(uint32_t*)&hp1);
        *(uint2*)&g_xlo[base + l * 4] = make_uint2(*(uint32_t*)&lp0, *(uint32_t*)&lp1);
    }
}

// Convert W (4 matrices, stacked into 256 rows: k|v|q|a) -> bf16 hi/lo
__global__ __launch_bounds__(256) void convert_w(
    const float* __restrict__ Wk, const float* __restrict__ Wv,
    const float* __restrict__ Wq, const float* __restrict__ Wa)
{
    int e4 = blockIdx.x * 256 + threadIdx.x;   // one per float4; 65536 total
    int base = e4 * 4;
    int row = base >> 10;       // 0..255
    int colk = base & 1023;
    int cb = row >> 6, n = row & 63;
    const float* W = (cb == 0) ? Wk : (cb == 1) ? Wv : (cb == 2) ? Wq : Wa;
    float4 v = *(const float4*)(W + (size_t)n * DD + colk);
    __nv_bfloat16 h0 = __float2bfloat16(v.x);
    __nv_bfloat16 h1 = __float2bfloat16(v.y);
    __nv_bfloat16 h2 = __float2bfloat16(v.z);
    __nv_bfloat16 h3 = __float2bfloat16(v.w);
    __nv_bfloat16 l0 = __float2bfloat16(v.x - __bfloat162float(h0));
    __nv_bfloat16 l1 = __float2bfloat16(v.y - __bfloat162float(h1));
    __nv_bfloat16 l2 = __float2bfloat16(v.z - __bfloat162float(h2));
    __nv_bfloat16 l3 = __float2bfloat16(v.w - __bfloat162float(h3));
    __nv_bfloat162 hp0 = __halves2bfloat162(h0, h1);
    __nv_bfloat162 hp1 = __halves2bfloat162(h2, h3);
    __nv_bfloat162 lp0 = __halves2bfloat162(l0, l1);
    __nv_bfloat162 lp1 = __halves2bfloat162(l2, l3);
    *(uint2*)&g_whi[(size_t)row * DD + colk] = make_uint2(*(uint32_t*)&hp0, *(uint32_t*)&hp1);
    *(uint2*)&g_wlo[(size_t)row * DD + colk] = make_uint2(*(uint32_t*)&lp0, *(uint32_t*)&lp1);
}

// ---------------------------------------------------------------------------
// Tensor-core GEMM: g_proj[32768,256] = X[32768,1024] @ Wcat^T
// 3x bf16 split: hh + hl + lh, fp32 accumulate via mma.sync.m16n8k16
// Block tile 128x128, BK=32, 256 threads (8 warps, warp tile 32x64).
// ---------------------------------------------------------------------------
#define GBM 128
#define GBN 128
#define GBK 32
#define SA  40    // smem row stride in bf16 (80B: 16B-aligned + conflict-free frags)

#define MMA16816(d, a, b0v, b1v)                                              \
    asm volatile("mma.sync.aligned.m16n8k16.row.col.f32.bf16.bf16.f32 "       \
                 "{%0,%1,%2,%3}, {%4,%5,%6,%7}, {%8,%9}, {%0,%1,%2,%3};"      \
                 : "+f"(d[0]), "+f"(d[1]), "+f"(d[2]), "+f"(d[3])             \
                 : "r"(a[0]), "r"(a[1]), "r"(a[2]), "r"(a[3]),                \
                   "r"(b0v), "r"(b1v));

__global__ __launch_bounds__(256) void mma_gemm() {
    __shared__ alignas(16) __nv_bfloat16 Ah[GBM * SA];
    __shared__ alignas(16) __nv_bfloat16 Al[GBM * SA];
    __shared__ alignas(16) __nv_bfloat16 Bh[GBN * SA];
    __shared__ alignas(16) __nv_bfloat16 Bl[GBN * SA];

    const int tid = threadIdx.x;
    const int wid = tid >> 5, lane = tid & 31;
    const int wm = wid & 3, wn = wid >> 2;        // warp tile at (wm*32, wn*64)
    const int row0 = blockIdx.x * GBM;
    const int col0 = blockIdx.y * GBN;
    const int g = lane >> 2, tg = lane & 3;       // groupID, threadInGroup

    float acc[2][8][4];
#pragma unroll
    for (int a = 0; a < 2; a++)
#pragma unroll
        for (int b = 0; b < 8; b++)
#pragma unroll
            for (int r = 0; r < 4; r++) acc[a][b][r] = 0.f;

    for (int kb = 0; kb < DD; kb += GBK) {
#pragma unroll
        for (int l = 0; l < 2; l++) {
            int f = tid + 256 * l;          // 0..511
            int r = f >> 2, kc = f & 3;     // row 0..127, 8-elem chunk 0..3
            size_t ga = (size_t)(row0 + r) * DD + kb + kc * 8;
            size_t gb = (size_t)(col0 + r) * DD + kb + kc * 8;
            *(uint4*)&Ah[r * SA + kc * 8] = *(const uint4*)&g_xhi[ga];
            *(uint4*)&Al[r * SA + kc * 8] = *(const uint4*)&g_xlo[ga];
            *(uint4*)&Bh[r * SA + kc * 8] = *(const uint4*)&g_whi[gb];
            *(uint4*)&Bl[r * SA + kc * 8] = *(const uint4*)&g_wlo[gb];
        }
        __syncthreads();

#pragma unroll
        for (int ks = 0; ks < GBK; ks += 16) {
            uint32_t afh[2][4], afl[2][4];
            const int kk2 = ks + 2 * tg;
#pragma unroll
            for (int ms = 0; ms < 2; ms++) {
                int rr = wm * 32 + ms * 16 + g;
                afh[ms][0] = *(const uint32_t*)&Ah[rr * SA + kk2];
                afh[ms][1] = *(const uint32_t*)&Ah[(rr + 8) * SA + kk2];
                afh[ms][2] = *(const uint32_t*)&Ah[rr * SA + kk2 + 8];
                afh[ms][3] = *(const uint32_t*)&Ah[(rr + 8) * SA + kk2 + 8];
                afl[ms][0] = *(const uint32_t*)&Al[rr * SA + kk2];
                afl[ms][1] = *(const uint32_t*)&Al[(rr + 8) * SA + kk2];
                afl[ms][2] = *(const uint32_t*)&Al[rr * SA + kk2 + 8];
                afl[ms][3] = *(const uint32_t*)&Al[(rr + 8) * SA + kk2 + 8];
            }
#pragma unroll
            for (int ns = 0; ns < 8; ns++) {
                int nr = wn * 64 + ns * 8 + g;
                uint32_t bh0 = *(const uint32_t*)&Bh[nr * SA + kk2];
                uint32_t bh1 = *(const uint32_t*)&Bh[nr * SA + kk2 + 8];
                uint32_t bl0 = *(const uint32_t*)&Bl[nr * SA + kk2];
                uint32_t bl1 = *(const uint32_t*)&Bl[nr * SA + kk2 + 8];
#pragma unroll
                for (int ms = 0; ms < 2; ms++) {
                    MMA16816(acc[ms][ns], afh[ms], bh0, bh1);
                    MMA16816(acc[ms][ns], afh[ms], bl0, bl1);
                    MMA16816(acc[ms][ns], afl[ms], bh0, bh1);
                }
            }
        }
        __syncthreads();
    }

    // epilogue: c0,c1 -> (m, n..n+1); c2,c3 -> (m+8, n..n+1)
#pragma unroll
    for (int ms = 0; ms < 2; ms++)
#pragma unroll
        for (int ns = 0; ns < 8; ns++) {
            int m = row0 + wm * 32 + ms * 16 + g;
            int n = col0 + wn * 64 + ns * 8 + tg * 2;
            *(float2*)&g_proj[(size_t)m * NC + n] =
                make_float2(acc[ms][ns][0], acc[ms][ns][1]);
            *(float2*)&g_proj[(size_t)(m + 8) * NC + n] =
                make_float2(acc[ms][ns][2], acc[ms][ns][3]);
        }
}

// ---------------------------------------------------------------------------
// Sequential scan. 64 blocks x 128 threads: block = 16 rows of one batch,
// 8 lanes per row (8 S elems each). Chain-shortened recurrence:
//   r_{t+1} = alpha * (S_t . k_{t+1}) + (1-alpha) * v_t * (k_t . k_{t+1})
// so the dot+reduce runs off the critical chain. sigmoid via tanh.approx.
// 4-deep register ring, prefetch distance 3 steps (covers L2 latency).
// ---------------------------------------------------------------------------
__device__ __forceinline__ float fast_tanh(float x) {
    float r;
    asm("tanh.approx.f32 %0, %1;" : "=f"(r) : "f"(x));
    return r;
}

__global__ __launch_bounds__(128) void scan_kernel(
    const float* __restrict__ S_in,
    const float* __restrict__ dA,
    const float* __restrict__ bA,
    float* __restrict__ out)   // [T*B*N] output, then [B*N*N] S_final
{
    const int b  = blockIdx.x >> 2;
    const int rb = blockIdx.x & 3;
    const int il = threadIdx.x >> 3;     // local row 0..15
    const int i  = rb * 16 + il;         // global row 0..63
    const int c  = threadIdx.x & 7;      // lane within row
    const int j0 = c << 3;

    float S[8];
    {
        const float* sp = S_in + ((size_t)b * NN + i) * NN + j0;
#pragma unroll
        for (int r = 0; r < 8; r++) S[r] = sp[r];
    }
    const float da = dA[i];
    const float ba = bA[i];

    float kb_[4][8], qb_[4][8], vb_[4], ab_[4];

    auto ldrow = [&](int t, int ph) {
        const float* P = g_proj + (size_t)(t * BB + b) * NC;
        float4 f0 = *(const float4*)(P + j0);
        float4 f1 = *(const float4*)(P + j0 + 4);
        kb_[ph][0] = f0.x; kb_[ph][1] = f0.y; kb_[ph][2] = f0.z; kb_[ph][3] = f0.w;
        kb_[ph][4] = f1.x; kb_[ph][5] = f1.y; kb_[ph][6] = f1.z; kb_[ph][7] = f1.w;
        float4 g0 = *(const float4*)(P + 128 + j0);
        float4 g1 = *(const float4*)(P + 128 + j0 + 4);
        qb_[ph][0] = g0.x; qb_[ph][1] = g0.y; qb_[ph][2] = g0.z; qb_[ph][3] = g0.w;
        qb_[ph][4] = g1.x; qb_[ph][5] = g1.y; qb_[ph][6] = g1.z; qb_[ph][7] = g1.w;
        vb_[ph] = P[64 + i];
        ab_[ph] = P[192 + i];
    };

    ldrow(0, 0); ldrow(1, 1); ldrow(2, 2);

    // r_0 = S_0 . k_0
    float r = 0.f;
#pragma unroll
    for (int j = 0; j < 8; j++) r = fmaf(S[j], kb_[0][j], r);
    r += __shfl_xor_sync(0xFFFFFFFFu, r, 1);
    r += __shfl_xor_sync(0xFFFFFFFFu, r, 2);
    r += __shfl_xor_sync(0xFFFFFFFFu, r, 4);

    auto step = [&](int t, int ph) {
        // prefetch t+3
        int tp = t + 3; if (tp > TT - 1) tp = TT - 1;
        ldrow(tp, (ph + 3) & 3);

        const float* kc = kb_[ph];
        const float* kn = kb_[(ph + 1) & 3];
        const float* qc = qb_[ph];
        const float vc = vb_[ph];

        // gate (critical chain): r -> alpha
        float xg = fmaf(da, r, ab_[ph] + ba);
        float alpha = fmaf(0.5f, fast_tanh(0.5f * xg), 0.5f);

        // off-chain dots on pre-update S with k_{t+1}
        float d1 = 0.f, u = 0.f;
#pragma unroll
        for (int j = 0; j < 8; j++) {
            d1 = fmaf(S[j], kn[j], d1);
            u  = fmaf(kc[j], kn[j], u);
        }
        d1 += __shfl_xor_sync(0xFFFFFFFFu, d1, 1);
        u  += __shfl_xor_sync(0xFFFFFFFFu, u, 1);
        d1 += __shfl_xor_sync(0xFFFFFFFFu, d1, 2);
        u  += __shfl_xor_sync(0xFFFFFFFFu, u, 2);
        d1 += __shfl_xor_sync(0xFFFFFFFFu, d1, 4);
        u  += __shfl_xor_sync(0xFFFFFFFFu, u, 4);

        float cc = (1.0f - alpha) * vc;

        // S update + out dot
        float o = 0.f;
#pragma unroll
        for (int j = 0; j < 8; j++) {
            S[j] = fmaf(alpha, S[j], cc * kc[j]);
            o = fmaf(S[j], qc[j], o);
        }
        o += __shfl_xor_sync(0xFFFFFFFFu, o, 1);
        o += __shfl_xor_sync(0xFFFFFFFFu, o, 2);
        o += __shfl_xor_sync(0xFFFFFFFFu, o, 4);

        // next-step retrieved (short chain)
        r = fmaf(alpha, d1, cc * u);

        if (c == 0) {
            float sig = fmaf(0.5f, fast_tanh(0.5f * o), 0.5f);
            out[(size_t)(t * BB + b) * NN + i] = o * o * sig;   // o * silu(o)
        }
    };

    for (int t0 = 0; t0 < TT; t0 += 4) {
        step(t0 + 0, 0);
        step(t0 + 1, 1);
        step(t0 + 2, 2);
        step(t0 + 3, 3);
    }

    float* so = out + (size_t)TT * BB * NN + ((size_t)b * NN + i) * NN + j0;
#pragma unroll
    for (int rji = 0; rji < 8; rji++) so[rji] = S[rji];
}

extern "C" void kernel_launch(void* const* d_in, const int* in_sizes, int n_in,
                              void* d_out, int out_size) {
    const float* x  = (const float*)d_in[0];
    const float* S  = (const float*)d_in[1];
    const float* Wk = (const float*)d_in[2];
    const float* Wv = (const float*)d_in[3];
    const float* Wq = (const float*)d_in[4];
    const float* Wa = (const float*)d_in[5];
    const float* da = (const float*)d_in[6];
    const float* ba = (const float*)d_in[7];
    float* out = (float*)d_out;

    convert_x<<<MT * DD / (256 * 16), 256>>>(x);
    convert_w<<<NC * DD / (256 * 4), 256>>>(Wk, Wv, Wq, Wa);
    dim3 ggrid(MT / GBM, NC / GBN);
    mma_gemm<<<ggrid, 256>>>();
    scan_kernel<<<BB * 4, 128>>>(S, da, ba, out);
}